// round 11
// baseline (speedup 1.0000x reference)
#include <cuda_runtime.h>
#include <math.h>

#define B_    4
#define N_    8192
#define F_    64
#define NIN_  67
#define NBLK  148
#define TPB   512
#define PPB   224            // points per block: 148*224 = 33152 >= 32768; 2*PPB = 448 = 14 FULL warps
#define NPTS  (B_ * N_)

#define S_OFF 0
#define F_OFF (B_ * N_)
#define C_OFF (B_ * N_ + B_ * N_ * F_)

// ---------------- scratch (no allocations allowed) ----------------
__device__ float             g_comp[B_][N_][3];  // compacted selected points
__device__ unsigned          g_arrive = 0;       // grid-barrier arrival counter
__device__ volatile unsigned g_gen    = 0;       // grid-barrier generation

// ---------------- f32x2 helpers (sm_103a packed fp32) ----------------
static __device__ __forceinline__ unsigned long long pack2(float lo, float hi) {
    unsigned long long r;
    asm("mov.b64 %0, {%1, %2};" : "=l"(r) : "f"(lo), "f"(hi));
    return r;
}
static __device__ __forceinline__ void unpack2(unsigned long long v, float& lo, float& hi) {
    asm("mov.b64 {%0, %1}, %2;" : "=f"(lo), "=f"(hi) : "l"(v));
}
static __device__ __forceinline__ unsigned long long ffma2(
    unsigned long long a, unsigned long long b, unsigned long long c) {
    unsigned long long d;
    asm("fma.rn.f32x2 %0, %1, %2, %3;" : "=l"(d) : "l"(a), "l"(b), "l"(c));
    return d;
}

static __device__ __forceinline__ bool read_mask(const void* m, int idx, int mode) {
    if (mode == 1) return ((const int*)m)[idx] != 0;
    if (mode == 2) return ((const float*)m)[idx] != 0.0f;
    return ((const unsigned char*)m)[idx] != 0;
}

// Replay-safe grid-wide barrier (all NBLK blocks co-resident: grid == 148 SMs,
// 1 block/SM). Every block calls this exactly once per kernel run.
static __device__ __forceinline__ void grid_barrier() {
    __syncthreads();
    if (threadIdx.x == 0) {
        unsigned gen = g_gen;
        __threadfence();                       // publish phase-1 writes
        if (atomicAdd(&g_arrive, 1u) == NBLK - 1u) {
            atomicExch(&g_arrive, 0u);         // reset for next graph replay
            __threadfence();
            g_gen = gen + 1u;                  // release
        } else {
            while (g_gen == gen) __nanosleep(40);
        }
        __threadfence();                       // acquire others' writes
    }
    __syncthreads();
}

// ---------------- the single fused kernel ----------------
__global__ void __launch_bounds__(TPB, 1)
fused_kernel(const float* __restrict__ points, const float* __restrict__ features,
             const void* __restrict__ mask,
             const float* __restrict__ W1, const float* __restrict__ b1,
             const float* __restrict__ W2, const float* __restrict__ b2,
             const float* __restrict__ W3, const float* __restrict__ b3,
             float* __restrict__ out) {
    // weights staged as f32x2 neuron pairs, 4 neurons per ulonglong2 (LDS.128)
    __shared__ ulonglong2         sW1[NIN_ * 16];  // [j][p]: neurons 4p..4p+3
    __shared__ unsigned long long sB1[32];
    __shared__ ulonglong2         sW2[64 * 8];     // [j][q]: neurons 4q..4q+3
    __shared__ unsigned long long sB2[16];
    __shared__ float              sW3[32];
    __shared__ float              sB3v;
    __shared__ int                s_fl[2];
    // finalize scratch
    __shared__ double sred[16], sred2[16];
    __shared__ int    wsum[16], woff[16];
    __shared__ int    s_nleaf, s_cnt;
    __shared__ double bSs, bSs2;

    const int tid  = threadIdx.x;
    const int bid  = blockIdx.x;
    const int lane = tid & 31, wid = tid >> 5;

    // ---- inline mask dtype detection (first 64 words; 0/1 data disambiguates) ----
    if (tid < 2) s_fl[tid] = 0;
    __syncthreads();
    {
        unsigned v = ((const unsigned*)mask)[tid & 63];
        if (v > 1u) atomicOr(&s_fl[0], 1);
        if (v != 0u && v != 0x3F800000u) atomicOr(&s_fl[1], 1);
    }

    // ---- weight staging ----
    for (int idx = tid; idx < NIN_ * 16; idx += TPB) {
        int j = idx >> 4, p = idx & 15;
        ulonglong2 w;
        w.x = pack2(W1[(4 * p + 0) * NIN_ + j], W1[(4 * p + 1) * NIN_ + j]);
        w.y = pack2(W1[(4 * p + 2) * NIN_ + j], W1[(4 * p + 3) * NIN_ + j]);
        sW1[idx] = w;
    }
    for (int idx = tid; idx < 64 * 8; idx += TPB) {
        int j = idx >> 3, p = idx & 7;
        ulonglong2 w;
        w.x = pack2(W2[(4 * p + 0) * 64 + j], W2[(4 * p + 1) * 64 + j]);
        w.y = pack2(W2[(4 * p + 2) * 64 + j], W2[(4 * p + 3) * 64 + j]);
        sW2[idx] = w;
    }
    if (tid < 32) sB1[tid] = pack2(b1[2 * tid], b1[2 * tid + 1]);
    if (tid < 16) sB2[tid] = pack2(b2[2 * tid], b2[2 * tid + 1]);
    if (tid < 32) sW3[tid] = W3[tid];
    if (tid == 0) sB3v = b3[0];

    // ---- feature passthrough: flat coalesced grid-stride copy (all blocks) ----
    {
        const float4* src = (const float4*)features;
        float4*       dst = (float4*)(out + F_OFF);
        const int total4 = (B_ * N_ * F_) / 4;  // 524288; 148*512 thr -> ~7 iters
        for (int i = bid * TPB + tid; i < total4; i += NBLK * TPB)
            dst[i] = src[i];
    }
    __syncthreads();
    const int mode = (!s_fl[0]) ? 1 : ((!s_fl[1]) ? 2 : 0);

    // ======== MLP: 2 threads per point, 224 points per block ========
    // even lane of pair: layer-1 neurons 0..31, layer-2 neurons 0..15
    // odd  lane of pair: layer-1 neurons 32..63, layer-2 neurons 16..31
    // Region covers threads 0..447 = warps 0..13 EXACTLY (no partial warps:
    // full-mask sync ops below require whole-warp participation).
    if (tid < 2 * PPB) {
        const int  pr    = bid * PPB + (tid >> 1);
        const bool valid = (pr < NPTS);
        const int  pt    = valid ? pr : (NPTS - 1);
        const int  oddt  = tid & 1;
        const bool m     = read_mask(mask, pt, mode);

        float score = 0.0f;
        if (__any_sync(0xFFFFFFFFu, m && valid)) {
            const float4* fv = (const float4*)(features + (size_t)pt * F_);
            const int hb = oddt ? 8 : 0;        // ulonglong2 offset into sW1 row
            const int qb = oddt ? 4 : 0;        // ulonglong2 offset into sW2 row

            unsigned long long acc[16];
#pragma unroll
            for (int p = 0; p < 16; p++) acc[p] = sB1[oddt * 16 + p];

#pragma unroll 4
            for (int c = 0; c < 16; c++) {
                float4 v = fv[c];
                float xs[4] = {v.x, v.y, v.z, v.w};
#pragma unroll
                for (int u = 0; u < 4; u++) {
                    unsigned long long xx = pack2(xs[u], xs[u]);
                    const ulonglong2* wrow = &sW1[(4 * c + u) * 16 + hb];
#pragma unroll
                    for (int p = 0; p < 8; p++) {
                        ulonglong2 w = wrow[p];
                        acc[2 * p]     = ffma2(xx, w.x, acc[2 * p]);
                        acc[2 * p + 1] = ffma2(xx, w.y, acc[2 * p + 1]);
                    }
                }
            }
            {   // xyz tail (inputs 64..66)
                const float* pp = points + (size_t)pt * 3;
                float ptv[3] = {pp[0], pp[1], pp[2]};
#pragma unroll
                for (int u = 0; u < 3; u++) {
                    unsigned long long xx = pack2(ptv[u], ptv[u]);
                    const ulonglong2* wrow = &sW1[(64 + u) * 16 + hb];
#pragma unroll
                    for (int p = 0; p < 8; p++) {
                        ulonglong2 w = wrow[p];
                        acc[2 * p]     = ffma2(xx, w.x, acc[2 * p]);
                        acc[2 * p + 1] = ffma2(xx, w.y, acc[2 * p + 1]);
                    }
                }
            }

            // relu -> this thread's 32 h1 values
            float h1[32];
#pragma unroll
            for (int p = 0; p < 16; p++) {
                float lo, hi;
                unpack2(acc[p], lo, hi);
                h1[2 * p]     = fmaxf(lo, 0.0f);
                h1[2 * p + 1] = fmaxf(hi, 0.0f);
            }

            // layer 2: each j's h1 value broadcast within the lane pair
            unsigned long long acc2[8];
#pragma unroll
            for (int q = 0; q < 8; q++) acc2[q] = sB2[oddt * 8 + q];
#pragma unroll 8
            for (int j = 0; j < 64; j++) {
                // h1[j] lives on pair-lane (j>>5): 0 = even (n 0..31), 1 = odd
                float hv = __shfl_sync(0xFFFFFFFFu, h1[j & 31], j >> 5, 2);
                unsigned long long hh = pack2(hv, hv);
                const ulonglong2* wrow = &sW2[j * 8 + qb];
#pragma unroll
                for (int q = 0; q < 4; q++) {
                    ulonglong2 w = wrow[q];
                    acc2[2 * q]     = ffma2(hh, w.x, acc2[2 * q]);
                    acc2[2 * q + 1] = ffma2(hh, w.y, acc2[2 * q + 1]);
                }
            }

            // layer 3 partial over this thread's 16 layer-2 neurons
            float z = 0.0f;
#pragma unroll
            for (int q = 0; q < 8; q++) {
                float lo, hi;
                unpack2(acc2[q], lo, hi);
                int n = oddt * 16 + 2 * q;
                z += fmaxf(lo, 0.0f) * sW3[n] + fmaxf(hi, 0.0f) * sW3[n + 1];
            }
            z += __shfl_xor_sync(0xFFFFFFFFu, z, 1);
            z += sB3v;
            score = 1.0f / (1.0f + expf(-z));
        }
        if (valid && !oddt)
            out[S_OFF + pt] = m ? score : 0.0f;
    }

    // ================= grid-wide barrier =================
    grid_barrier();

    if (bid >= B_) return;

    // ================= finalize: batch b = bid, 512 threads =================
    const int    b      = bid;
    float*       scores = out + S_OFF + b * N_;
    const float* pts    = points + (size_t)b * N_ * 3;

    // ---- n_leaf (16 mask entries per thread) ----
    {
        int lc = 0;
#pragma unroll
        for (int k = 0; k < 16; k++)
            lc += read_mask(mask, b * N_ + tid * 16 + k, mode) ? 1 : 0;
#pragma unroll
        for (int o = 16; o > 0; o >>= 1) lc += __shfl_down_sync(0xFFFFFFFFu, lc, o);
        if (lane == 0) wsum[wid] = lc;
        __syncthreads();
        if (tid == 0) {
            int s = 0;
#pragma unroll
            for (int w = 0; w < 16; w++) s += wsum[w];
            s_nleaf = s;
        }
        __syncthreads();
    }
    const int n_leaf = s_nleaf;
    __syncthreads();

    // ---- load scores, apply n_leaf<10 zeroing, sums ----
    float sv[16];
    {
        const float4* s4 = (const float4*)scores + tid * 4;
#pragma unroll
        for (int q = 0; q < 4; q++) {
            float4 v = s4[q];
            sv[4 * q + 0] = v.x; sv[4 * q + 1] = v.y;
            sv[4 * q + 2] = v.z; sv[4 * q + 3] = v.w;
        }
    }
    const float zfac = (n_leaf < 10) ? 0.0f : 1.0f;
    double ls = 0.0, ls2 = 0.0;
#pragma unroll
    for (int k = 0; k < 16; k++) {
        float s = sv[k] * zfac;
        sv[k] = s;
        ls += s; ls2 += (double)s * (double)s;
    }
    if (n_leaf < 10) {
        float4 z4 = make_float4(0.f, 0.f, 0.f, 0.f);
        float4* s4 = (float4*)scores + tid * 4;
#pragma unroll
        for (int q = 0; q < 4; q++) s4[q] = z4;
    }
#pragma unroll
    for (int o = 16; o > 0; o >>= 1) {
        ls  += __shfl_down_sync(0xFFFFFFFFu, ls, o);
        ls2 += __shfl_down_sync(0xFFFFFFFFu, ls2, o);
    }
    if (lane == 0) { sred[wid] = ls; sred2[wid] = ls2; }
    __syncthreads();
    if (tid == 0) {
        double a = 0.0, c = 0.0;
#pragma unroll
        for (int w = 0; w < 16; w++) { a += sred[w]; c += sred2[w]; }
        bSs = a; bSs2 = c;
    }
    __syncthreads();

    // ---- selection (> 0.7), stable compaction by index ----
    int c = 0;
#pragma unroll
    for (int k = 0; k < 16; k++) c += (sv[k] > 0.7f) ? 1 : 0;
    int incl = c;
#pragma unroll
    for (int o = 1; o < 32; o <<= 1) {
        int t = __shfl_up_sync(0xFFFFFFFFu, incl, o);
        if (lane >= o) incl += t;
    }
    if (lane == 31) wsum[wid] = incl;
    __syncthreads();
    if (tid == 0) {
        int run = 0;
#pragma unroll
        for (int w = 0; w < 16; w++) { int t = wsum[w]; woff[w] = run; run += t; }
        s_cnt = run;
    }
    __syncthreads();
    int       pos = incl - c + woff[wid];
    const int cnt = s_cnt;
#pragma unroll
    for (int k = 0; k < 16; k++) {
        if (sv[k] > 0.7f) {
            int n = tid * 16 + k;
            g_comp[b][pos][0] = pts[n * 3 + 0];
            g_comp[b][pos][1] = pts[n * 3 + 1];
            g_comp[b][pos][2] = pts[n * 3 + 2];
            pos++;
        }
    }
    __syncthreads();

    // ---- consecutive-distance variance among selected points ----
    double ld = 0.0, ld2 = 0.0;
    for (int k = tid; k < cnt - 1; k += TPB) {
        float dx = g_comp[b][k + 1][0] - g_comp[b][k][0];
        float dy = g_comp[b][k + 1][1] - g_comp[b][k][1];
        float dz = g_comp[b][k + 1][2] - g_comp[b][k][2];
        float dd = sqrtf(dx * dx + dy * dy + dz * dz);
        ld += dd; ld2 += (double)dd * (double)dd;
    }
#pragma unroll
    for (int o = 16; o > 0; o >>= 1) {
        ld  += __shfl_down_sync(0xFFFFFFFFu, ld, o);
        ld2 += __shfl_down_sync(0xFFFFFFFFu, ld2, o);
    }
    if (lane == 0) { sred[wid] = ld; sred2[wid] = ld2; }
    __syncthreads();
    if (tid == 0) {
        double Sd = 0.0, Sd2 = 0.0;
#pragma unroll
        for (int w = 0; w < 16; w++) { Sd += sred[w]; Sd2 += sred2[w]; }

        const double Ss = bSs, Ss2 = bSs2;
        double nl    = (double)n_leaf;
        double meanS = Ss / fmax(nl, 1.0);
        float  clarity = (float)((Ss2 - nl * meanS * meanS) / fmax(nl - 1.0, 1.0));
        int np = cnt - 1; if (np < 0) np = 0;
        double dnp   = (double)np;
        double meanD = Sd / fmax(dnp, 1.0);
        float  dvar  = (float)((Sd2 - dnp * meanD * meanD) / fmax(dnp - 1.0, 1.0));
        float cont = 1.0f / (dvar + 1e-8f);
        cont = fminf(fmaxf(cont, 0.0f), 1.0f);
        if (!(cnt > 5)) cont = 0.0f;
        float conf = fminf(fmaxf(clarity * cont, 0.0f), 1.0f);
        if (n_leaf == 0) conf = 0.0f;
        out[C_OFF + b] = conf;
    }
}

// ---------------- launch ----------------
extern "C" void kernel_launch(void* const* d_in, const int* in_sizes, int n_in,
                              void* d_out, int out_size) {
    const float* points   = (const float*)d_in[0];
    const float* features = (const float*)d_in[1];
    const void*  mask     = d_in[2];
    const float* W1 = (const float*)d_in[3];
    const float* b1 = (const float*)d_in[4];
    const float* W2 = (const float*)d_in[5];
    const float* b2 = (const float*)d_in[6];
    const float* W3 = (const float*)d_in[7];
    const float* b3 = (const float*)d_in[8];
    float* out = (float*)d_out;

    fused_kernel<<<NBLK, TPB>>>(points, features, mask,
                                W1, b1, W2, b2, W3, b3, out);
}